// round 2
// baseline (speedup 1.0000x reference)
#include <cuda_runtime.h>
#include <math.h>

#define F_IN 512
#define HID  256
#define NCLS 40
#define MAXN 100000
#define MAXE 1600000

// ---- scratch (static __device__ arrays; no allocation allowed) ----
__device__ float g_h1  [(size_t)MAXN * HID];   // X @ W1
__device__ float g_agg1[(size_t)MAXN * HID];   // aggregated layer-1 (then relu'd in place)
__device__ float g_h2  [(size_t)MAXN * NCLS];  // x1 @ W2
__device__ float g_agg2[(size_t)MAXN * NCLS];  // aggregated layer-2 logits (pre-bias)
__device__ float g_deg [MAXN];
__device__ float g_dinv[MAXN];
__device__ float g_coeff[MAXE];

// ---------------- prep kernels ----------------
__global__ void k_zero_deg(int M) {
    int i = blockIdx.x * 256 + threadIdx.x;
    if (i < M) g_deg[i] = 0.0f;
}

// edge_index arrives as int32 (JAX x64 disabled: jnp.int64 request silently yields int32)
__global__ void k_prep(const int* __restrict__ ei, int E) {
    int e = blockIdx.x * 256 + threadIdx.x;
    if (e >= E) return;
    atomicAdd(&g_deg[ei[E + e]], 1.0f);
}

__global__ void k_dinv(int M) {
    int i = blockIdx.x * 256 + threadIdx.x;
    if (i < M) g_dinv[i] = rsqrtf(g_deg[i] + 1.0f);
}

__global__ void k_coeff(const int* __restrict__ ei, int E) {
    int e = blockIdx.x * 256 + threadIdx.x;
    if (e >= E) return;
    g_coeff[e] = g_dinv[ei[e]] * g_dinv[ei[E + e]];
}

// ---------------- GEMM1: h1 = X[M,512] @ W1[512,256]; agg1 = h1 * dinv^2 ----------------
// 64x64 tile, BK=16, 256 threads, 4x4 microtile.
__global__ void k_gemm1(const float* __restrict__ A, const float* __restrict__ B, int M) {
    __shared__ float As[16][64];
    __shared__ float Bs[16][64];
    int tid = threadIdx.x;
    int tx = tid & 15, ty = tid >> 4;
    int bm = blockIdx.y * 64, bn = blockIdx.x * 64;

    int ar  = tid >> 2, ac4 = tid & 3;    // A loader: row ar (0..63), float4 col ac4 (0..3)
    int brw = tid >> 4, bc4 = tid & 15;   // B loader: row brw (0..15), float4 col bc4 (0..15)

    float acc[4][4];
#pragma unroll
    for (int i = 0; i < 4; i++)
#pragma unroll
        for (int j = 0; j < 4; j++) acc[i][j] = 0.0f;

    for (int k0 = 0; k0 < F_IN; k0 += 16) {
        float4 a4 = make_float4(0.f, 0.f, 0.f, 0.f);
        int arow = bm + ar;
        if (arow < M)
            a4 = *(const float4*)(A + (size_t)arow * F_IN + k0 + ac4 * 4);
        As[ac4 * 4 + 0][ar] = a4.x;
        As[ac4 * 4 + 1][ar] = a4.y;
        As[ac4 * 4 + 2][ar] = a4.z;
        As[ac4 * 4 + 3][ar] = a4.w;

        float4 b4 = *(const float4*)(B + (size_t)(k0 + brw) * HID + bn + bc4 * 4);
        *(float4*)&Bs[brw][bc4 * 4] = b4;
        __syncthreads();

#pragma unroll
        for (int kk = 0; kk < 16; kk++) {
            float4 a = *(float4*)&As[kk][ty * 4];
            float4 b = *(float4*)&Bs[kk][tx * 4];
            float av[4] = {a.x, a.y, a.z, a.w};
            float bv[4] = {b.x, b.y, b.z, b.w};
#pragma unroll
            for (int i = 0; i < 4; i++)
#pragma unroll
                for (int j = 0; j < 4; j++)
                    acc[i][j] = fmaf(av[i], bv[j], acc[i][j]);
        }
        __syncthreads();
    }

#pragma unroll
    for (int i = 0; i < 4; i++) {
        int row = bm + ty * 4 + i;
        if (row >= M) continue;
        float dv = g_dinv[row];
        float d2 = dv * dv;
        int col = bn + tx * 4;
        float4 c = make_float4(acc[i][0], acc[i][1], acc[i][2], acc[i][3]);
        *(float4*)(g_h1 + (size_t)row * HID + col) = c;
        float4 cs = make_float4(c.x * d2, c.y * d2, c.z * d2, c.w * d2);
        *(float4*)(g_agg1 + (size_t)row * HID + col) = cs;  // self-loop init (no zeroing needed)
    }
}

// ---------------- scatter layer 1: agg1[dst] += h1[src] * coeff ----------------
// one thread per (edge, float4); 64 float4 per edge
__global__ void k_scatter1(const int* __restrict__ ei, int E) {
    long long t = (long long)blockIdx.x * 256 + threadIdx.x;
    long long total = (long long)E * 64;
    if (t >= total) return;
    int e = (int)(t >> 6);
    int f = (int)(t & 63) * 4;
    int s = ei[e], d = ei[E + e];
    float c = g_coeff[e];
    float4 v = *(const float4*)(g_h1 + (size_t)s * HID + f);
    float* p = g_agg1 + (size_t)d * HID + f;
    atomicAdd(p + 0, v.x * c);
    atomicAdd(p + 1, v.y * c);
    atomicAdd(p + 2, v.z * c);
    atomicAdd(p + 3, v.w * c);
}

// ---------------- finalize layer 1: x1 = relu(agg1 + b1), in place ----------------
__global__ void k_finalize1(const float* __restrict__ b1, int M) {
    long long i = (long long)blockIdx.x * 256 + threadIdx.x;  // float4 index
    if (i >= (long long)M * (HID / 4)) return;
    int c4 = (int)(i & (HID / 4 - 1));
    float4 v = *(float4*)(g_agg1 + i * 4);
    float4 b = *(const float4*)(b1 + c4 * 4);
    v.x = fmaxf(v.x + b.x, 0.0f);
    v.y = fmaxf(v.y + b.y, 0.0f);
    v.z = fmaxf(v.z + b.z, 0.0f);
    v.w = fmaxf(v.w + b.w, 0.0f);
    *(float4*)(g_agg1 + i * 4) = v;
}

// ---------------- GEMM2: h2 = x1[M,256] @ W2[256,40]; agg2 = h2 * dinv^2 ----------------
// 128-row tiles, BK=32, 256 threads (tx 0..7 -> 5 cols each, ty 0..31 -> 4 rows each)
__global__ void k_gemm2(const float* __restrict__ W2, int M) {
    __shared__ float As[32][128];
    __shared__ float Ws[32][NCLS];
    int tid = threadIdx.x;
    int tx = tid & 7, ty = tid >> 3;
    int bm = blockIdx.x * 128;

    float acc[4][5];
#pragma unroll
    for (int i = 0; i < 4; i++)
#pragma unroll
        for (int j = 0; j < 5; j++) acc[i][j] = 0.0f;

    for (int k0 = 0; k0 < HID; k0 += 32) {
#pragma unroll
        for (int i = 0; i < 4; i++) {
            int lin = tid + i * 256;       // 0..1023
            int r = lin >> 3, c4 = lin & 7;
            int row = bm + r;
            float4 a4 = make_float4(0.f, 0.f, 0.f, 0.f);
            if (row < M)
                a4 = *(const float4*)(g_agg1 + (size_t)row * HID + k0 + c4 * 4);
            As[c4 * 4 + 0][r] = a4.x;
            As[c4 * 4 + 1][r] = a4.y;
            As[c4 * 4 + 2][r] = a4.z;
            As[c4 * 4 + 3][r] = a4.w;
        }
#pragma unroll
        for (int i = 0; i < 5; i++) {
            int lin = tid + i * 256;       // 0..1279
            int r = lin / NCLS, c = lin % NCLS;
            Ws[r][c] = W2[(size_t)(k0 + r) * NCLS + c];
        }
        __syncthreads();

#pragma unroll
        for (int kk = 0; kk < 32; kk++) {
            float4 a = *(float4*)&As[kk][ty * 4];
            float av[4] = {a.x, a.y, a.z, a.w};
            float w[5];
#pragma unroll
            for (int j = 0; j < 5; j++) w[j] = Ws[kk][tx * 5 + j];
#pragma unroll
            for (int i = 0; i < 4; i++)
#pragma unroll
                for (int j = 0; j < 5; j++)
                    acc[i][j] = fmaf(av[i], w[j], acc[i][j]);
        }
        __syncthreads();
    }

#pragma unroll
    for (int i = 0; i < 4; i++) {
        int row = bm + ty * 4 + i;
        if (row >= M) continue;
        float dv = g_dinv[row];
        float d2 = dv * dv;
#pragma unroll
        for (int j = 0; j < 5; j++) {
            int col = tx * 5 + j;
            float v = acc[i][j];
            g_h2[(size_t)row * NCLS + col] = v;
            g_agg2[(size_t)row * NCLS + col] = v * d2;  // self-loop init
        }
    }
}

// ---------------- scatter layer 2: agg2[dst] += h2[src] * coeff ----------------
// one thread per (edge, float4); 10 float4 per edge
__global__ void k_scatter2(const int* __restrict__ ei, int E) {
    long long t = (long long)blockIdx.x * 256 + threadIdx.x;
    long long total = (long long)E * 10;
    if (t >= total) return;
    int e = (int)(t / 10);
    int f = (int)(t % 10) * 4;
    int s = ei[e], d = ei[E + e];
    float c = g_coeff[e];
    float4 v = *(const float4*)(g_h2 + (size_t)s * NCLS + f);
    float* p = g_agg2 + (size_t)d * NCLS + f;
    atomicAdd(p + 0, v.x * c);
    atomicAdd(p + 1, v.y * c);
    atomicAdd(p + 2, v.z * c);
    atomicAdd(p + 3, v.w * c);
}

// ---------------- softmax: logits = agg2 + b2 -> out[0:M*40]=log_softmax, out[M*40:]=softmax ----------------
__global__ void k_softmax(const float* __restrict__ b2, float* __restrict__ out, int M, int write_soft) {
    int warp = threadIdx.x >> 5, lane = threadIdx.x & 31;
    int n = blockIdx.x * 8 + warp;
    if (n >= M) return;
    const float* row = g_agg2 + (size_t)n * NCLS;
    float v0 = row[lane] + b2[lane];                 // lane < 32 < 40, always valid
    bool has1 = lane < (NCLS - 32);
    float v1 = has1 ? (row[lane + 32] + b2[lane + 32]) : -INFINITY;
    float m = fmaxf(v0, v1);
#pragma unroll
    for (int o = 16; o; o >>= 1) m = fmaxf(m, __shfl_xor_sync(0xffffffffu, m, o));
    float s = expf(v0 - m) + (has1 ? expf(v1 - m) : 0.0f);
#pragma unroll
    for (int o = 16; o; o >>= 1) s += __shfl_xor_sync(0xffffffffu, s, o);
    float lse = m + logf(s);
    float l0 = v0 - lse;
    out[(size_t)n * NCLS + lane] = l0;
    if (write_soft) out[(size_t)M * NCLS + (size_t)n * NCLS + lane] = expf(l0);
    if (has1) {
        float l1 = v1 - lse;
        out[(size_t)n * NCLS + lane + 32] = l1;
        if (write_soft) out[(size_t)M * NCLS + (size_t)n * NCLS + lane + 32] = expf(l1);
    }
}

extern "C" void kernel_launch(void* const* d_in, const int* in_sizes, int n_in,
                              void* d_out, int out_size) {
    const float* features = (const float*)d_in[0];
    const float* W1       = (const float*)d_in[1];
    const float* b1       = (const float*)d_in[2];
    const float* W2       = (const float*)d_in[3];
    const float* b2       = (const float*)d_in[4];
    const int*   ei       = (const int*)d_in[5];   // int32 (JAX x64 disabled)

    int M = in_sizes[0] / F_IN;   // 100000
    int E = in_sizes[5] / 2;      // 1600000
    float* out = (float*)d_out;
    int write_soft = (out_size >= 2 * M * NCLS) ? 1 : 0;

    // degree / normalization
    k_zero_deg<<<(M + 255) / 256, 256>>>(M);
    k_prep<<<(E + 255) / 256, 256>>>(ei, E);
    k_dinv<<<(M + 255) / 256, 256>>>(M);
    k_coeff<<<(E + 255) / 256, 256>>>(ei, E);

    // layer 1
    dim3 g1(HID / 64, (M + 63) / 64);
    k_gemm1<<<g1, 256>>>(features, W1, M);
    long long t1 = (long long)E * 64;
    k_scatter1<<<(unsigned)((t1 + 255) / 256), 256>>>(ei, E);
    long long tf = (long long)M * (HID / 4);
    k_finalize1<<<(unsigned)((tf + 255) / 256), 256>>>(b1, M);

    // layer 2
    k_gemm2<<<(M + 127) / 128, 256>>>(W2, M);
    long long t2 = (long long)E * 10;
    k_scatter2<<<(unsigned)((t2 + 255) / 256), 256>>>(ei, E);

    // outputs
    k_softmax<<<(M + 7) / 8, 256>>>(b2, out, M, write_soft);
}

// round 4
// speedup vs baseline: 1.5316x; 1.5316x over previous
#include <cuda_runtime.h>
#include <math.h>

#define F_IN 512
#define HID  256
#define NCLS 40
#define MAXN 100000
#define MAXE 1600000

// ---- scratch (static __device__ arrays; no allocation allowed) ----
__device__ float g_h1  [(size_t)MAXN * HID];   // X @ W1
__device__ float g_agg1[(size_t)MAXN * HID];   // aggregated layer-1 (pre-bias/relu)
__device__ float g_h2  [(size_t)MAXN * NCLS];  // x1 @ W2
__device__ float g_agg2[(size_t)MAXN * NCLS];  // aggregated layer-2 logits (pre-bias)
__device__ float g_deg [MAXN];
__device__ float g_dinv[MAXN];
__device__ float g_coeff[MAXE];

__device__ __forceinline__ void red_add_v4(float* p, float x, float y, float z, float w) {
    asm volatile("red.relaxed.gpu.global.add.v4.f32 [%0], {%1, %2, %3, %4};"
                 :: "l"(p), "f"(x), "f"(y), "f"(z), "f"(w) : "memory");
}

// ---------------- prep kernels ----------------
__global__ void k_zero_deg(int M) {
    int i = blockIdx.x * 256 + threadIdx.x;
    if (i < M) g_deg[i] = 0.0f;
}

// edge_index is int32 (JAX x64 disabled)
__global__ void k_prep(const int* __restrict__ ei, int E) {
    int e = blockIdx.x * 256 + threadIdx.x;
    if (e >= E) return;
    atomicAdd(&g_deg[ei[E + e]], 1.0f);
}

__global__ void k_dinv(int M) {
    int i = blockIdx.x * 256 + threadIdx.x;
    if (i < M) g_dinv[i] = rsqrtf(g_deg[i] + 1.0f);
}

__global__ void k_coeff(const int* __restrict__ ei, int E) {
    int e = blockIdx.x * 256 + threadIdx.x;
    if (e >= E) return;
    g_coeff[e] = g_dinv[ei[e]] * g_dinv[ei[E + e]];
}

// ---------------- GEMM1: h1 = X[M,512] @ W1[512,256]; agg1 = h1 * dinv^2 ----------------
// 128x128 tile, BK=16, 256 threads, 8x8 microtile.
__global__ void __launch_bounds__(256) k_gemm1(const float* __restrict__ A,
                                               const float* __restrict__ B, int M) {
    __shared__ float As[16][132];   // padded: kills store-bank conflicts
    __shared__ float Bs[16][128];
    int tid = threadIdx.x;
    int bm = blockIdx.y * 128, bn = blockIdx.x * 128;
    int tx = tid & 15, ty = tid >> 4;        // 16x16 thread grid, 8x8 micro

    // A loader: two float4 per thread per tile
    int ar0 = tid >> 2;                      // 0..63
    int akc = tid & 3;                       // 0..3 (float4 within BK=16)
    // B loader: ALL 256 threads load two float4 (512 total = full 16x128 tile)
    int brw = tid >> 4;                      // 0..15 (k-row)
    int bcl = (tid & 15) * 8;                // 0,8,...,120 (col start)

    float acc[8][8];
#pragma unroll
    for (int i = 0; i < 8; i++)
#pragma unroll
        for (int j = 0; j < 8; j++) acc[i][j] = 0.0f;

    for (int k0 = 0; k0 < F_IN; k0 += 16) {
        // load A rows [bm..bm+127], k [k0..k0+15]
#pragma unroll
        for (int h = 0; h < 2; h++) {
            int row = ar0 + h * 64;
            float4 a4 = make_float4(0.f, 0.f, 0.f, 0.f);
            if (bm + row < M)
                a4 = *(const float4*)(A + (size_t)(bm + row) * F_IN + k0 + akc * 4);
            As[akc * 4 + 0][row] = a4.x;
            As[akc * 4 + 1][row] = a4.y;
            As[akc * 4 + 2][row] = a4.z;
            As[akc * 4 + 3][row] = a4.w;
        }
        // load B rows [k0..k0+15], cols [bn..bn+127]
        {
            const float* bp = B + (size_t)(k0 + brw) * HID + bn + bcl;
            float4 b0 = *(const float4*)(bp + 0);
            float4 b1v = *(const float4*)(bp + 4);
            *(float4*)&Bs[brw][bcl + 0] = b0;
            *(float4*)&Bs[brw][bcl + 4] = b1v;
        }
        __syncthreads();

#pragma unroll
        for (int kk = 0; kk < 16; kk++) {
            float4 aA = *(float4*)&As[kk][ty * 8];
            float4 aB = *(float4*)&As[kk][ty * 8 + 4];
            float4 bA = *(float4*)&Bs[kk][tx * 8];
            float4 bB = *(float4*)&Bs[kk][tx * 8 + 4];
            float av[8] = {aA.x, aA.y, aA.z, aA.w, aB.x, aB.y, aB.z, aB.w};
            float bv[8] = {bA.x, bA.y, bA.z, bA.w, bB.x, bB.y, bB.z, bB.w};
#pragma unroll
            for (int i = 0; i < 8; i++)
#pragma unroll
                for (int j = 0; j < 8; j++)
                    acc[i][j] = fmaf(av[i], bv[j], acc[i][j]);
        }
        __syncthreads();
    }

#pragma unroll
    for (int i = 0; i < 8; i++) {
        int row = bm + ty * 8 + i;
        if (row >= M) continue;
        float dv = g_dinv[row];
        float d2 = dv * dv;
#pragma unroll
        for (int jc = 0; jc < 2; jc++) {
            int col = bn + tx * 8 + jc * 4;
            float4 c = make_float4(acc[i][jc * 4 + 0], acc[i][jc * 4 + 1],
                                   acc[i][jc * 4 + 2], acc[i][jc * 4 + 3]);
            *(float4*)(g_h1 + (size_t)row * HID + col) = c;
            float4 cs = make_float4(c.x * d2, c.y * d2, c.z * d2, c.w * d2);
            *(float4*)(g_agg1 + (size_t)row * HID + col) = cs;  // self-loop init
        }
    }
}

// ---------------- scatter layer 1: agg1[dst] += h1[src] * coeff ----------------
__global__ void k_scatter1(const int* __restrict__ ei, int E) {
    long long t = (long long)blockIdx.x * 256 + threadIdx.x;
    if (t >= (long long)E * 64) return;
    int e = (int)(t >> 6);
    int f = (int)(t & 63) * 4;
    int s = ei[e], d = ei[E + e];
    float c = g_coeff[e];
    float4 v = *(const float4*)(g_h1 + (size_t)s * HID + f);
    float* p = g_agg1 + (size_t)d * HID + f;
    red_add_v4(p, v.x * c, v.y * c, v.z * c, v.w * c);
}

// ---------------- GEMM2: h2 = relu(agg1+b1) @ W2; agg2 = h2 * dinv^2 ----------------
// bias+relu fused into the A-tile loader (finalize1 kernel eliminated)
__global__ void __launch_bounds__(256) k_gemm2(const float* __restrict__ W2,
                                               const float* __restrict__ b1, int M) {
    __shared__ float As[32][128];
    __shared__ float Ws[32][NCLS];
    int tid = threadIdx.x;
    int tx = tid & 7, ty = tid >> 3;
    int bm = blockIdx.x * 128;

    float acc[4][5];
#pragma unroll
    for (int i = 0; i < 4; i++)
#pragma unroll
        for (int j = 0; j < 5; j++) acc[i][j] = 0.0f;

    for (int k0 = 0; k0 < HID; k0 += 32) {
#pragma unroll
        for (int i = 0; i < 4; i++) {
            int lin = tid + i * 256;       // 0..1023
            int r = lin >> 3, c4 = lin & 7;
            int row = bm + r;
            float4 a4 = make_float4(0.f, 0.f, 0.f, 0.f);
            if (row < M) {
                a4 = *(const float4*)(g_agg1 + (size_t)row * HID + k0 + c4 * 4);
                float4 bb = *(const float4*)(b1 + k0 + c4 * 4);
                a4.x = fmaxf(a4.x + bb.x, 0.0f);
                a4.y = fmaxf(a4.y + bb.y, 0.0f);
                a4.z = fmaxf(a4.z + bb.z, 0.0f);
                a4.w = fmaxf(a4.w + bb.w, 0.0f);
            }
            As[c4 * 4 + 0][r] = a4.x;
            As[c4 * 4 + 1][r] = a4.y;
            As[c4 * 4 + 2][r] = a4.z;
            As[c4 * 4 + 3][r] = a4.w;
        }
#pragma unroll
        for (int i = 0; i < 5; i++) {
            int lin = tid + i * 256;       // 0..1279
            int r = lin / NCLS, c = lin % NCLS;
            Ws[r][c] = W2[(size_t)(k0 + r) * NCLS + c];
        }
        __syncthreads();

#pragma unroll
        for (int kk = 0; kk < 32; kk++) {
            float4 a = *(float4*)&As[kk][ty * 4];
            float av[4] = {a.x, a.y, a.z, a.w};
            float w[5];
#pragma unroll
            for (int j = 0; j < 5; j++) w[j] = Ws[kk][tx * 5 + j];
#pragma unroll
            for (int i = 0; i < 4; i++)
#pragma unroll
                for (int j = 0; j < 5; j++)
                    acc[i][j] = fmaf(av[i], w[j], acc[i][j]);
        }
        __syncthreads();
    }

#pragma unroll
    for (int i = 0; i < 4; i++) {
        int row = bm + ty * 4 + i;
        if (row >= M) continue;
        float dv = g_dinv[row];
        float d2 = dv * dv;
#pragma unroll
        for (int j = 0; j < 5; j++) {
            int col = tx * 5 + j;
            float v = acc[i][j];
            g_h2[(size_t)row * NCLS + col] = v;
            g_agg2[(size_t)row * NCLS + col] = v * d2;  // self-loop init
        }
    }
}

// ---------------- scatter layer 2: agg2[dst] += h2[src] * coeff ----------------
__global__ void k_scatter2(const int* __restrict__ ei, int E) {
    long long t = (long long)blockIdx.x * 256 + threadIdx.x;
    if (t >= (long long)E * 10) return;
    int e = (int)(t / 10);
    int f = (int)(t % 10) * 4;
    int s = ei[e], d = ei[E + e];
    float c = g_coeff[e];
    float4 v = *(const float4*)(g_h2 + (size_t)s * NCLS + f);
    float* p = g_agg2 + (size_t)d * NCLS + f;
    red_add_v4(p, v.x * c, v.y * c, v.z * c, v.w * c);
}

// ---------------- softmax: logits = agg2 + b2 -> out[0:M*40]=log_softmax, out[M*40:]=softmax ----------------
__global__ void k_softmax(const float* __restrict__ b2, float* __restrict__ out, int M, int write_soft) {
    int warp = threadIdx.x >> 5, lane = threadIdx.x & 31;
    int n = blockIdx.x * 8 + warp;
    if (n >= M) return;
    const float* row = g_agg2 + (size_t)n * NCLS;
    float v0 = row[lane] + b2[lane];
    bool has1 = lane < (NCLS - 32);
    float v1 = has1 ? (row[lane + 32] + b2[lane + 32]) : -INFINITY;
    float m = fmaxf(v0, v1);
#pragma unroll
    for (int o = 16; o; o >>= 1) m = fmaxf(m, __shfl_xor_sync(0xffffffffu, m, o));
    float s = expf(v0 - m) + (has1 ? expf(v1 - m) : 0.0f);
#pragma unroll
    for (int o = 16; o; o >>= 1) s += __shfl_xor_sync(0xffffffffu, s, o);
    float lse = m + logf(s);
    float l0 = v0 - lse;
    out[(size_t)n * NCLS + lane] = l0;
    if (write_soft) out[(size_t)M * NCLS + (size_t)n * NCLS + lane] = expf(l0);
    if (has1) {
        float l1 = v1 - lse;
        out[(size_t)n * NCLS + lane + 32] = l1;
        if (write_soft) out[(size_t)M * NCLS + (size_t)n * NCLS + lane + 32] = expf(l1);
    }
}

extern "C" void kernel_launch(void* const* d_in, const int* in_sizes, int n_in,
                              void* d_out, int out_size) {
    const float* features = (const float*)d_in[0];
    const float* W1       = (const float*)d_in[1];
    const float* b1       = (const float*)d_in[2];
    const float* W2       = (const float*)d_in[3];
    const float* b2       = (const float*)d_in[4];
    const int*   ei       = (const int*)d_in[5];

    int M = in_sizes[0] / F_IN;   // 100000
    int E = in_sizes[5] / 2;      // 1600000
    float* out = (float*)d_out;
    int write_soft = (out_size >= 2 * M * NCLS) ? 1 : 0;

    // degree / normalization  (gemm1 placed 4th so ncu -s5-c1 captures it)
    k_zero_deg<<<(M + 255) / 256, 256>>>(M);                 // launch 1
    k_prep<<<(E + 255) / 256, 256>>>(ei, E);                 // launch 2
    k_dinv<<<(M + 255) / 256, 256>>>(M);                     // launch 3

    dim3 g1(HID / 128, (M + 127) / 128);
    k_gemm1<<<g1, 256>>>(features, W1, M);                   // launch 4  <- profiled
    k_coeff<<<(E + 255) / 256, 256>>>(ei, E);                // launch 5

    long long t1 = (long long)E * 64;
    k_scatter1<<<(unsigned)((t1 + 255) / 256), 256>>>(ei, E);// launch 6

    k_gemm2<<<(M + 127) / 128, 256>>>(W2, b1, M);            // launch 7
    long long t2 = (long long)E * 10;
    k_scatter2<<<(unsigned)((t2 + 255) / 256), 256>>>(ei, E);// launch 8

    k_softmax<<<(M + 7) / 8, 256>>>(b2, out, M, write_soft); // launch 9
}

// round 6
// speedup vs baseline: 1.9516x; 1.2743x over previous
#include <cuda_runtime.h>
#include <cuda_bf16.h>
#include <math.h>
#include <stdint.h>

#define F_IN 512
#define HID  256
#define NCLS 40
#define MAXN 100000
#define MAXE 1600000

// ---- scratch ----
__device__ float g_h1  [(size_t)MAXN * HID];
__device__ float g_agg1[(size_t)MAXN * HID];
__device__ float g_h2  [(size_t)MAXN * NCLS];
__device__ float g_agg2[(size_t)MAXN * NCLS];
__device__ float g_deg [MAXN];
__device__ float g_dinv[MAXN];
__device__ float g_coeff[MAXE];
__device__ __nv_bfloat16 g_w1hi[(size_t)HID * F_IN];  // [n][k] transposed
__device__ __nv_bfloat16 g_w1lo[(size_t)HID * F_IN];

__device__ __forceinline__ void red_add_v4(float* p, float x, float y, float z, float w) {
    asm volatile("red.relaxed.gpu.global.add.v4.f32 [%0], {%1, %2, %3, %4};"
                 :: "l"(p), "f"(x), "f"(y), "f"(z), "f"(w) : "memory");
}

#define MMA_BF16(c, a, b) \
    asm volatile("mma.sync.aligned.m16n8k16.row.col.f32.bf16.bf16.f32 " \
                 "{%0,%1,%2,%3}, {%4,%5,%6,%7}, {%8,%9}, {%0,%1,%2,%3};" \
                 : "+f"((c)[0]), "+f"((c)[1]), "+f"((c)[2]), "+f"((c)[3]) \
                 : "r"((a)[0]), "r"((a)[1]), "r"((a)[2]), "r"((a)[3]), \
                   "r"((b)[0]), "r"((b)[1]))

__device__ __forceinline__ uint32_t pack2(__nv_bfloat16 a, __nv_bfloat16 b) {
    return (uint32_t)__bfloat16_as_ushort(a) | ((uint32_t)__bfloat16_as_ushort(b) << 16);
}

// ---------------- prep: split W1 into bf16 hi/lo (transposed) + zero deg ----------------
__global__ void k_split_zero(const float* __restrict__ W1) {
    int i = blockIdx.x * 256 + threadIdx.x;   // 0 .. 512*256-1
    if (i < MAXN) g_deg[i] = 0.0f;
    if (i < F_IN * HID) {
        int k = i >> 8, n = i & 255;
        float w = W1[(size_t)k * HID + n];
        __nv_bfloat16 hi = __float2bfloat16_rn(w);
        __nv_bfloat16 lo = __float2bfloat16_rn(w - __bfloat162float(hi));
        g_w1hi[(size_t)n * F_IN + k] = hi;
        g_w1lo[(size_t)n * F_IN + k] = lo;
    }
}

__global__ void k_prep(const int* __restrict__ ei, int E) {
    int e = blockIdx.x * 256 + threadIdx.x;
    if (e >= E) return;
    atomicAdd(&g_deg[ei[E + e]], 1.0f);
}

__global__ void k_dinv(int M) {
    int i = blockIdx.x * 256 + threadIdx.x;
    if (i < M) g_dinv[i] = rsqrtf(g_deg[i] + 1.0f);
}

__global__ void k_coeff(const int* __restrict__ ei, int E) {
    int e = blockIdx.x * 256 + threadIdx.x;
    if (e >= E) return;
    g_coeff[e] = g_dinv[ei[e]] * g_dinv[ei[E + e]];
}

// ---------------- GEMM1: mma.sync bf16x3. 128x128 block, BK=32, 8 warps (2m x 4n) ----------------
#define ASTR 40   // smem row stride in bf16 (20 words -> conflict-free frag loads)
__global__ void __launch_bounds__(256) k_gemm1(const float* __restrict__ A, int M) {
    __shared__ __nv_bfloat16 Ahi[128][ASTR], Alo[128][ASTR];
    __shared__ __nv_bfloat16 Bhi[128][ASTR], Blo[128][ASTR];
    int tid = threadIdx.x, lane = tid & 31, wid = tid >> 5;
    int bm = blockIdx.y * 128, bn = blockIdx.x * 128;
    int m0 = (wid & 1) * 64, n0 = (wid >> 1) * 32;

    float c[4][4][4];
#pragma unroll
    for (int i = 0; i < 4; i++)
#pragma unroll
        for (int j = 0; j < 4; j++)
#pragma unroll
            for (int r = 0; r < 4; r++) c[i][j][r] = 0.0f;

    for (int s = 0; s < F_IN / 32; s++) {
        int k0 = s * 32;
        // A tile: 128 rows x 32 k, fp32 -> bf16 hi/lo
#pragma unroll
        for (int i = 0; i < 4; i++) {
            int ch = tid + i * 256;          // 0..1023 float4 chunks
            int m = ch >> 3, k4 = ch & 7;
            float4 a = make_float4(0.f, 0.f, 0.f, 0.f);
            if (bm + m < M)
                a = *(const float4*)(A + (size_t)(bm + m) * F_IN + k0 + k4 * 4);
            __nv_bfloat16 hx = __float2bfloat16_rn(a.x), hy = __float2bfloat16_rn(a.y);
            __nv_bfloat16 hz = __float2bfloat16_rn(a.z), hw = __float2bfloat16_rn(a.w);
            __nv_bfloat16 lx = __float2bfloat16_rn(a.x - __bfloat162float(hx));
            __nv_bfloat16 ly = __float2bfloat16_rn(a.y - __bfloat162float(hy));
            __nv_bfloat16 lz = __float2bfloat16_rn(a.z - __bfloat162float(hz));
            __nv_bfloat16 lw = __float2bfloat16_rn(a.w - __bfloat162float(hw));
            *(uint2*)&Ahi[m][k4 * 4] = make_uint2(pack2(hx, hy), pack2(hz, hw));
            *(uint2*)&Alo[m][k4 * 4] = make_uint2(pack2(lx, ly), pack2(lz, lw));
        }
        // B tile: 128 n-rows x 32 k, pre-split bf16
#pragma unroll
        for (int i = 0; i < 2; i++) {
            int ch = tid + i * 256;          // 0..511 16B chunks
            int n = ch >> 2, kc = ch & 3;
            size_t gi = (size_t)(bn + n) * F_IN + k0 + kc * 8;
            *(uint4*)&Bhi[n][kc * 8] = *(const uint4*)(g_w1hi + gi);
            *(uint4*)&Blo[n][kc * 8] = *(const uint4*)(g_w1lo + gi);
        }
        __syncthreads();

#pragma unroll
        for (int kk = 0; kk < 32; kk += 16) {
            uint32_t ah[4][4], al[4][4], bh[4][2], bl[4][2];
            int kcol = kk + (lane & 3) * 2;
#pragma unroll
            for (int tm = 0; tm < 4; tm++) {
                int r = m0 + tm * 16 + (lane >> 2);
                ah[tm][0] = *(uint32_t*)&Ahi[r][kcol];
                ah[tm][1] = *(uint32_t*)&Ahi[r + 8][kcol];
                ah[tm][2] = *(uint32_t*)&Ahi[r][kcol + 8];
                ah[tm][3] = *(uint32_t*)&Ahi[r + 8][kcol + 8];
                al[tm][0] = *(uint32_t*)&Alo[r][kcol];
                al[tm][1] = *(uint32_t*)&Alo[r + 8][kcol];
                al[tm][2] = *(uint32_t*)&Alo[r][kcol + 8];
                al[tm][3] = *(uint32_t*)&Alo[r + 8][kcol + 8];
            }
#pragma unroll
            for (int tn = 0; tn < 4; tn++) {
                int n = n0 + tn * 8 + (lane >> 2);
                bh[tn][0] = *(uint32_t*)&Bhi[n][kcol];
                bh[tn][1] = *(uint32_t*)&Bhi[n][kcol + 8];
                bl[tn][0] = *(uint32_t*)&Blo[n][kcol];
                bl[tn][1] = *(uint32_t*)&Blo[n][kcol + 8];
            }
#pragma unroll
            for (int tm = 0; tm < 4; tm++)
#pragma unroll
                for (int tn = 0; tn < 4; tn++) {
                    MMA_BF16(c[tm][tn], ah[tm], bh[tn]);
                    MMA_BF16(c[tm][tn], ah[tm], bl[tn]);
                    MMA_BF16(c[tm][tn], al[tm], bh[tn]);
                }
        }
        __syncthreads();
    }

    // epilogue: c0,c1 -> (row, col..col+1); c2,c3 -> (row+8, ...)
#pragma unroll
    for (int tm = 0; tm < 4; tm++) {
        int row0 = bm + m0 + tm * 16 + (lane >> 2);
#pragma unroll
        for (int h = 0; h < 2; h++) {
            int row = row0 + h * 8;
            if (row >= M) continue;
            float dv = g_dinv[row];
            float d2 = dv * dv;
#pragma unroll
            for (int tn = 0; tn < 4; tn++) {
                int col = bn + n0 + tn * 8 + (lane & 3) * 2;
                float2 v = make_float2(c[tm][tn][h * 2 + 0], c[tm][tn][h * 2 + 1]);
                *(float2*)(g_h1 + (size_t)row * HID + col) = v;
                *(float2*)(g_agg1 + (size_t)row * HID + col) = make_float2(v.x * d2, v.y * d2);
            }
        }
    }
}

// ---------------- scatter layer 1 ----------------
__global__ void k_scatter1(const int* __restrict__ ei, int E) {
    long long t = (long long)blockIdx.x * 256 + threadIdx.x;
    if (t >= (long long)E * 64) return;
    int e = (int)(t >> 6);
    int f = (int)(t & 63) * 4;
    int s = ei[e], d = ei[E + e];
    float c = g_coeff[e];
    float4 v = *(const float4*)(g_h1 + (size_t)s * HID + f);
    float* p = g_agg1 + (size_t)d * HID + f;
    red_add_v4(p, v.x * c, v.y * c, v.z * c, v.w * c);
}

// ---------------- GEMM2 (bias+relu fused A-loader) ----------------
__global__ void __launch_bounds__(256) k_gemm2(const float* __restrict__ W2,
                                               const float* __restrict__ b1, int M) {
    __shared__ float As[32][128];
    __shared__ float Ws[32][NCLS];
    int tid = threadIdx.x;
    int tx = tid & 7, ty = tid >> 3;
    int bm = blockIdx.x * 128;

    float acc[4][5];
#pragma unroll
    for (int i = 0; i < 4; i++)
#pragma unroll
        for (int j = 0; j < 5; j++) acc[i][j] = 0.0f;

    for (int k0 = 0; k0 < HID; k0 += 32) {
#pragma unroll
        for (int i = 0; i < 4; i++) {
            int lin = tid + i * 256;
            int r = lin >> 3, c4 = lin & 7;
            int row = bm + r;
            float4 a4 = make_float4(0.f, 0.f, 0.f, 0.f);
            if (row < M) {
                a4 = *(const float4*)(g_agg1 + (size_t)row * HID + k0 + c4 * 4);
                float4 bb = *(const float4*)(b1 + k0 + c4 * 4);
                a4.x = fmaxf(a4.x + bb.x, 0.0f);
                a4.y = fmaxf(a4.y + bb.y, 0.0f);
                a4.z = fmaxf(a4.z + bb.z, 0.0f);
                a4.w = fmaxf(a4.w + bb.w, 0.0f);
            }
            As[c4 * 4 + 0][r] = a4.x;
            As[c4 * 4 + 1][r] = a4.y;
            As[c4 * 4 + 2][r] = a4.z;
            As[c4 * 4 + 3][r] = a4.w;
        }
#pragma unroll
        for (int i = 0; i < 5; i++) {
            int lin = tid + i * 256;
            int r = lin / NCLS, c = lin % NCLS;
            Ws[r][c] = W2[(size_t)(k0 + r) * NCLS + c];
        }
        __syncthreads();

#pragma unroll
        for (int kk = 0; kk < 32; kk++) {
            float4 a = *(float4*)&As[kk][ty * 4];
            float av[4] = {a.x, a.y, a.z, a.w};
            float w[5];
#pragma unroll
            for (int j = 0; j < 5; j++) w[j] = Ws[kk][tx * 5 + j];
#pragma unroll
            for (int i = 0; i < 4; i++)
#pragma unroll
                for (int j = 0; j < 5; j++)
                    acc[i][j] = fmaf(av[i], w[j], acc[i][j]);
        }
        __syncthreads();
    }

#pragma unroll
    for (int i = 0; i < 4; i++) {
        int row = bm + ty * 4 + i;
        if (row >= M) continue;
        float dv = g_dinv[row];
        float d2 = dv * dv;
#pragma unroll
        for (int j = 0; j < 5; j++) {
            int col = tx * 5 + j;
            float v = acc[i][j];
            g_h2[(size_t)row * NCLS + col] = v;
            g_agg2[(size_t)row * NCLS + col] = v * d2;
        }
    }
}

// ---------------- scatter layer 2 ----------------
__global__ void k_scatter2(const int* __restrict__ ei, int E) {
    long long t = (long long)blockIdx.x * 256 + threadIdx.x;
    if (t >= (long long)E * 10) return;
    int e = (int)(t / 10);
    int f = (int)(t % 10) * 4;
    int s = ei[e], d = ei[E + e];
    float c = g_coeff[e];
    float4 v = *(const float4*)(g_h2 + (size_t)s * NCLS + f);
    float* p = g_agg2 + (size_t)d * NCLS + f;
    red_add_v4(p, v.x * c, v.y * c, v.z * c, v.w * c);
}

// ---------------- softmax ----------------
__global__ void k_softmax(const float* __restrict__ b2, float* __restrict__ out, int M, int write_soft) {
    int warp = threadIdx.x >> 5, lane = threadIdx.x & 31;
    int n = blockIdx.x * 8 + warp;
    if (n >= M) return;
    const float* row = g_agg2 + (size_t)n * NCLS;
    float v0 = row[lane] + b2[lane];
    bool has1 = lane < (NCLS - 32);
    float v1 = has1 ? (row[lane + 32] + b2[lane + 32]) : -INFINITY;
    float m = fmaxf(v0, v1);
#pragma unroll
    for (int o = 16; o; o >>= 1) m = fmaxf(m, __shfl_xor_sync(0xffffffffu, m, o));
    float s = expf(v0 - m) + (has1 ? expf(v1 - m) : 0.0f);
#pragma unroll
    for (int o = 16; o; o >>= 1) s += __shfl_xor_sync(0xffffffffu, s, o);
    float lse = m + logf(s);
    float l0 = v0 - lse;
    out[(size_t)n * NCLS + lane] = l0;
    if (write_soft) out[(size_t)M * NCLS + (size_t)n * NCLS + lane] = expf(l0);
    if (has1) {
        float l1 = v1 - lse;
        out[(size_t)n * NCLS + lane + 32] = l1;
        if (write_soft) out[(size_t)M * NCLS + (size_t)n * NCLS + lane + 32] = expf(l1);
    }
}

extern "C" void kernel_launch(void* const* d_in, const int* in_sizes, int n_in,
                              void* d_out, int out_size) {
    const float* features = (const float*)d_in[0];
    const float* W1       = (const float*)d_in[1];
    const float* b1       = (const float*)d_in[2];
    const float* W2       = (const float*)d_in[3];
    const float* b2       = (const float*)d_in[4];
    const int*   ei       = (const int*)d_in[5];

    int M = in_sizes[0] / F_IN;
    int E = in_sizes[5] / 2;
    float* out = (float*)d_out;
    int write_soft = (out_size >= 2 * M * NCLS) ? 1 : 0;

    k_split_zero<<<(F_IN * HID + 255) / 256, 256>>>(W1);     // launch 1
    k_prep<<<(E + 255) / 256, 256>>>(ei, E);                 // launch 2
    k_dinv<<<(M + 255) / 256, 256>>>(M);                     // launch 3

    dim3 g1(HID / 128, (M + 127) / 128);
    k_gemm1<<<g1, 256>>>(features, M);                       // launch 4  <- profiled
    k_coeff<<<(E + 255) / 256, 256>>>(ei, E);                // launch 5

    long long t1 = (long long)E * 64;
    k_scatter1<<<(unsigned)((t1 + 255) / 256), 256>>>(ei, E);// launch 6

    k_gemm2<<<(M + 127) / 128, 256>>>(W2, b1, M);            // launch 7
    long long t2 = (long long)E * 10;
    k_scatter2<<<(unsigned)((t2 + 255) / 256), 256>>>(ei, E);// launch 8

    k_softmax<<<(M + 7) / 8, 256>>>(b2, out, M, write_soft); // launch 9
}

// round 7
// speedup vs baseline: 2.4731x; 1.2672x over previous
#include <cuda_runtime.h>
#include <cuda_bf16.h>
#include <math.h>
#include <stdint.h>

#define F_IN 512
#define HID  256
#define NCLS 40
#define MAXN 100000
#define MAXE 1600000

// ---- scratch ----
__device__ float g_h1  [(size_t)MAXN * HID];
__device__ float g_agg1[(size_t)MAXN * HID];
__device__ float g_h2  [(size_t)MAXN * NCLS];
__device__ float g_agg2[(size_t)MAXN * NCLS];
__device__ float g_dinv[MAXN];
__device__ int   g_cnt [MAXN];
__device__ int   g_rowstart[MAXN + 1];
__device__ int   g_cursor[MAXN];
__device__ int   g_se[MAXE];      // src per bucketed edge
__device__ float g_ce[MAXE];      // coeff per bucketed edge
__device__ int   g_bsum[128];
__device__ __nv_bfloat16 g_w1hi[(size_t)HID * F_IN];  // [n][k] transposed
__device__ __nv_bfloat16 g_w1lo[(size_t)HID * F_IN];

#define MMA_BF16(c, a, b) \
    asm volatile("mma.sync.aligned.m16n8k16.row.col.f32.bf16.bf16.f32 " \
                 "{%0,%1,%2,%3}, {%4,%5,%6,%7}, {%8,%9}, {%0,%1,%2,%3};" \
                 : "+f"((c)[0]), "+f"((c)[1]), "+f"((c)[2]), "+f"((c)[3]) \
                 : "r"((a)[0]), "r"((a)[1]), "r"((a)[2]), "r"((a)[3]), \
                   "r"((b)[0]), "r"((b)[1]))

__device__ __forceinline__ uint32_t pack2(__nv_bfloat16 a, __nv_bfloat16 b) {
    return (uint32_t)__bfloat16_as_ushort(a) | ((uint32_t)__bfloat16_as_ushort(b) << 16);
}

// ---------------- prep: split W1 (transposed hi/lo) + zero counters ----------------
__global__ void k_split_zero(const float* __restrict__ W1) {
    int i = blockIdx.x * 256 + threadIdx.x;   // grid covers 131072 >= MAXN
    if (i < MAXN) g_cnt[i] = 0;
    if (i < F_IN * HID) {
        int k = i >> 8, n = i & 255;
        float w = W1[(size_t)k * HID + n];
        __nv_bfloat16 hi = __float2bfloat16_rn(w);
        __nv_bfloat16 lo = __float2bfloat16_rn(w - __bfloat162float(hi));
        g_w1hi[(size_t)n * F_IN + k] = hi;
        g_w1lo[(size_t)n * F_IN + k] = lo;
    }
}

__global__ void k_count(const int* __restrict__ ei, int E) {
    int e = blockIdx.x * 256 + threadIdx.x;
    if (e >= E) return;
    atomicAdd(&g_cnt[ei[E + e]], 1);
}

// exclusive scan over g_cnt -> g_rowstart (3 kernels)
__global__ void k_scan1(int M) {
    __shared__ int sd[1024];
    int t = threadIdx.x, b = blockIdx.x;
    int i = b * 1024 + t;
    int v = (i < M) ? g_cnt[i] : 0;
    sd[t] = v;
    __syncthreads();
    for (int off = 1; off < 1024; off <<= 1) {
        int x = (t >= off) ? sd[t - off] : 0;
        __syncthreads();
        sd[t] += x;
        __syncthreads();
    }
    if (i < M) g_rowstart[i] = sd[t] - v;   // partial exclusive
    if (t == 1023) g_bsum[b] = sd[1023];
}

__global__ void k_scan2(int nb) {
    __shared__ int sd[128];
    int t = threadIdx.x;
    int v = (t < nb) ? g_bsum[t] : 0;
    sd[t] = v;
    __syncthreads();
    for (int off = 1; off < 128; off <<= 1) {
        int x = (t >= off) ? sd[t - off] : 0;
        __syncthreads();
        sd[t] += x;
        __syncthreads();
    }
    if (t < nb) g_bsum[t] = sd[t] - v;      // exclusive
}

__global__ void k_scan3(int M, int E) {
    int i = blockIdx.x * 256 + threadIdx.x;
    if (i >= M) return;
    int rs = g_rowstart[i] + g_bsum[i >> 10];
    g_rowstart[i] = rs;
    g_cursor[i] = rs;
    g_dinv[i] = rsqrtf((float)g_cnt[i] + 1.0f);
    if (i == 0) g_rowstart[M] = E;
}

__global__ void k_bucket(const int* __restrict__ ei, int E) {
    int e = blockIdx.x * 256 + threadIdx.x;
    if (e >= E) return;
    int s = ei[e], d = ei[E + e];
    int pos = atomicAdd(&g_cursor[d], 1);
    g_se[pos] = s;
    g_ce[pos] = g_dinv[s] * g_dinv[d];
}

// ---------------- GEMM1: mma.sync bf16x3. 128x128 block, BK=32, 8 warps (2m x 4n) ----------------
#define ASTR 40
__global__ void __launch_bounds__(256) k_gemm1(const float* __restrict__ A, int M) {
    __shared__ __nv_bfloat16 Ahi[128][ASTR], Alo[128][ASTR];
    __shared__ __nv_bfloat16 Bhi[128][ASTR], Blo[128][ASTR];
    int tid = threadIdx.x, lane = tid & 31, wid = tid >> 5;
    int bm = blockIdx.y * 128, bn = blockIdx.x * 128;
    int m0 = (wid & 1) * 64, n0 = (wid >> 1) * 32;

    float c[4][4][4];
#pragma unroll
    for (int i = 0; i < 4; i++)
#pragma unroll
        for (int j = 0; j < 4; j++)
#pragma unroll
            for (int r = 0; r < 4; r++) c[i][j][r] = 0.0f;

    for (int s = 0; s < F_IN / 32; s++) {
        int k0 = s * 32;
#pragma unroll
        for (int i = 0; i < 4; i++) {
            int ch = tid + i * 256;
            int m = ch >> 3, k4 = ch & 7;
            float4 a = make_float4(0.f, 0.f, 0.f, 0.f);
            if (bm + m < M)
                a = *(const float4*)(A + (size_t)(bm + m) * F_IN + k0 + k4 * 4);
            __nv_bfloat16 hx = __float2bfloat16_rn(a.x), hy = __float2bfloat16_rn(a.y);
            __nv_bfloat16 hz = __float2bfloat16_rn(a.z), hw = __float2bfloat16_rn(a.w);
            __nv_bfloat16 lx = __float2bfloat16_rn(a.x - __bfloat162float(hx));
            __nv_bfloat16 ly = __float2bfloat16_rn(a.y - __bfloat162float(hy));
            __nv_bfloat16 lz = __float2bfloat16_rn(a.z - __bfloat162float(hz));
            __nv_bfloat16 lw = __float2bfloat16_rn(a.w - __bfloat162float(hw));
            *(uint2*)&Ahi[m][k4 * 4] = make_uint2(pack2(hx, hy), pack2(hz, hw));
            *(uint2*)&Alo[m][k4 * 4] = make_uint2(pack2(lx, ly), pack2(lz, lw));
        }
#pragma unroll
        for (int i = 0; i < 2; i++) {
            int ch = tid + i * 256;
            int n = ch >> 2, kc = ch & 3;
            size_t gi = (size_t)(bn + n) * F_IN + k0 + kc * 8;
            *(uint4*)&Bhi[n][kc * 8] = *(const uint4*)(g_w1hi + gi);
            *(uint4*)&Blo[n][kc * 8] = *(const uint4*)(g_w1lo + gi);
        }
        __syncthreads();

#pragma unroll
        for (int kk = 0; kk < 32; kk += 16) {
            uint32_t ah[4][4], al[4][4], bh[4][2], bl[4][2];
            int kcol = kk + (lane & 3) * 2;
#pragma unroll
            for (int tm = 0; tm < 4; tm++) {
                int r = m0 + tm * 16 + (lane >> 2);
                ah[tm][0] = *(uint32_t*)&Ahi[r][kcol];
                ah[tm][1] = *(uint32_t*)&Ahi[r + 8][kcol];
                ah[tm][2] = *(uint32_t*)&Ahi[r][kcol + 8];
                ah[tm][3] = *(uint32_t*)&Ahi[r + 8][kcol + 8];
                al[tm][0] = *(uint32_t*)&Alo[r][kcol];
                al[tm][1] = *(uint32_t*)&Alo[r + 8][kcol];
                al[tm][2] = *(uint32_t*)&Alo[r][kcol + 8];
                al[tm][3] = *(uint32_t*)&Alo[r + 8][kcol + 8];
            }
#pragma unroll
            for (int tn = 0; tn < 4; tn++) {
                int n = n0 + tn * 8 + (lane >> 2);
                bh[tn][0] = *(uint32_t*)&Bhi[n][kcol];
                bh[tn][1] = *(uint32_t*)&Bhi[n][kcol + 8];
                bl[tn][0] = *(uint32_t*)&Blo[n][kcol];
                bl[tn][1] = *(uint32_t*)&Blo[n][kcol + 8];
            }
#pragma unroll
            for (int tm = 0; tm < 4; tm++)
#pragma unroll
                for (int tn = 0; tn < 4; tn++) {
                    MMA_BF16(c[tm][tn], ah[tm], bh[tn]);
                    MMA_BF16(c[tm][tn], ah[tm], bl[tn]);
                    MMA_BF16(c[tm][tn], al[tm], bh[tn]);
                }
        }
        __syncthreads();
    }

#pragma unroll
    for (int tm = 0; tm < 4; tm++) {
        int row0 = bm + m0 + tm * 16 + (lane >> 2);
#pragma unroll
        for (int h = 0; h < 2; h++) {
            int row = row0 + h * 8;
            if (row >= M) continue;
#pragma unroll
            for (int tn = 0; tn < 4; tn++) {
                int col = bn + n0 + tn * 8 + (lane & 3) * 2;
                float2 v = make_float2(c[tm][tn][h * 2 + 0], c[tm][tn][h * 2 + 1]);
                *(float2*)(g_h1 + (size_t)row * HID + col) = v;
            }
        }
    }
}

// ---------------- agg layer 1: block per dst node, no atomics ----------------
__global__ void __launch_bounds__(256) k_agg1(int M) {
    int n = blockIdx.x;
    int tid = threadIdx.x;
    int st = g_rowstart[n], en = g_rowstart[n + 1];
    float dv = g_dinv[n];
    float acc = g_h1[(size_t)n * HID + tid] * (dv * dv);   // self loop
    int e = st;
    for (; e + 1 < en; e += 2) {
        int s0 = g_se[e], s1 = g_se[e + 1];
        float c0 = g_ce[e], c1 = g_ce[e + 1];
        float v0 = g_h1[(size_t)s0 * HID + tid];
        float v1 = g_h1[(size_t)s1 * HID + tid];
        acc += v0 * c0 + v1 * c1;
    }
    if (e < en) acc += g_h1[(size_t)g_se[e] * HID + tid] * g_ce[e];
    g_agg1[(size_t)n * HID + tid] = acc;
}

// ---------------- GEMM2 (bias+relu fused A-loader) ----------------
__global__ void __launch_bounds__(256) k_gemm2(const float* __restrict__ W2,
                                               const float* __restrict__ b1, int M) {
    __shared__ float As[32][128];
    __shared__ float Ws[32][NCLS];
    int tid = threadIdx.x;
    int tx = tid & 7, ty = tid >> 3;
    int bm = blockIdx.x * 128;

    float acc[4][5];
#pragma unroll
    for (int i = 0; i < 4; i++)
#pragma unroll
        for (int j = 0; j < 5; j++) acc[i][j] = 0.0f;

    for (int k0 = 0; k0 < HID; k0 += 32) {
#pragma unroll
        for (int i = 0; i < 4; i++) {
            int lin = tid + i * 256;
            int r = lin >> 3, c4 = lin & 7;
            int row = bm + r;
            float4 a4 = make_float4(0.f, 0.f, 0.f, 0.f);
            if (row < M) {
                a4 = *(const float4*)(g_agg1 + (size_t)row * HID + k0 + c4 * 4);
                float4 bb = *(const float4*)(b1 + k0 + c4 * 4);
                a4.x = fmaxf(a4.x + bb.x, 0.0f);
                a4.y = fmaxf(a4.y + bb.y, 0.0f);
                a4.z = fmaxf(a4.z + bb.z, 0.0f);
                a4.w = fmaxf(a4.w + bb.w, 0.0f);
            }
            As[c4 * 4 + 0][r] = a4.x;
            As[c4 * 4 + 1][r] = a4.y;
            As[c4 * 4 + 2][r] = a4.z;
            As[c4 * 4 + 3][r] = a4.w;
        }
#pragma unroll
        for (int i = 0; i < 5; i++) {
            int lin = tid + i * 256;
            int r = lin / NCLS, c = lin % NCLS;
            Ws[r][c] = W2[(size_t)(k0 + r) * NCLS + c];
        }
        __syncthreads();

#pragma unroll
        for (int kk = 0; kk < 32; kk++) {
            float4 a = *(float4*)&As[kk][ty * 4];
            float av[4] = {a.x, a.y, a.z, a.w};
            float w[5];
#pragma unroll
            for (int j = 0; j < 5; j++) w[j] = Ws[kk][tx * 5 + j];
#pragma unroll
            for (int i = 0; i < 4; i++)
#pragma unroll
                for (int j = 0; j < 5; j++)
                    acc[i][j] = fmaf(av[i], w[j], acc[i][j]);
        }
        __syncthreads();
    }

#pragma unroll
    for (int i = 0; i < 4; i++) {
        int row = bm + ty * 4 + i;
        if (row >= M) continue;
#pragma unroll
        for (int j = 0; j < 5; j++)
            g_h2[(size_t)row * NCLS + tx * 5 + j] = acc[i][j];
    }
}

// ---------------- agg layer 2: warp per dst node, no atomics ----------------
__global__ void __launch_bounds__(256) k_agg2(int M) {
    int warp = threadIdx.x >> 5, lane = threadIdx.x & 31;
    int n = blockIdx.x * 8 + warp;
    if (n >= M) return;
    int st = g_rowstart[n], en = g_rowstart[n + 1];
    float dv = g_dinv[n];
    float d2 = dv * dv;
    const float* hn = g_h2 + (size_t)n * NCLS;
    float a0 = hn[lane] * d2;
    float a1 = (lane < 8) ? hn[32 + lane] * d2 : 0.0f;
    for (int e = st; e < en; e++) {
        int s = g_se[e];
        float cc = g_ce[e];
        const float* hs = g_h2 + (size_t)s * NCLS;
        a0 += hs[lane] * cc;
        if (lane < 8) a1 += hs[32 + lane] * cc;
    }
    g_agg2[(size_t)n * NCLS + lane] = a0;
    if (lane < 8) g_agg2[(size_t)n * NCLS + 32 + lane] = a1;
}

// ---------------- softmax ----------------
__global__ void k_softmax(const float* __restrict__ b2, float* __restrict__ out, int M, int write_soft) {
    int warp = threadIdx.x >> 5, lane = threadIdx.x & 31;
    int n = blockIdx.x * 8 + warp;
    if (n >= M) return;
    const float* row = g_agg2 + (size_t)n * NCLS;
    float v0 = row[lane] + b2[lane];
    bool has1 = lane < (NCLS - 32);
    float v1 = has1 ? (row[lane + 32] + b2[lane + 32]) : -INFINITY;
    float m = fmaxf(v0, v1);
#pragma unroll
    for (int o = 16; o; o >>= 1) m = fmaxf(m, __shfl_xor_sync(0xffffffffu, m, o));
    float s = expf(v0 - m) + (has1 ? expf(v1 - m) : 0.0f);
#pragma unroll
    for (int o = 16; o; o >>= 1) s += __shfl_xor_sync(0xffffffffu, s, o);
    float lse = m + logf(s);
    float l0 = v0 - lse;
    out[(size_t)n * NCLS + lane] = l0;
    if (write_soft) out[(size_t)M * NCLS + (size_t)n * NCLS + lane] = expf(l0);
    if (has1) {
        float l1 = v1 - lse;
        out[(size_t)n * NCLS + lane + 32] = l1;
        if (write_soft) out[(size_t)M * NCLS + (size_t)n * NCLS + lane + 32] = expf(l1);
    }
}

extern "C" void kernel_launch(void* const* d_in, const int* in_sizes, int n_in,
                              void* d_out, int out_size) {
    const float* features = (const float*)d_in[0];
    const float* W1       = (const float*)d_in[1];
    const float* b1       = (const float*)d_in[2];
    const float* W2       = (const float*)d_in[3];
    const float* b2       = (const float*)d_in[4];
    const int*   ei       = (const int*)d_in[5];

    int M = in_sizes[0] / F_IN;
    int E = in_sizes[5] / 2;
    float* out = (float*)d_out;
    int write_soft = (out_size >= 2 * M * NCLS) ? 1 : 0;
    int nb = (M + 1023) / 1024;

    k_split_zero<<<(F_IN * HID + 255) / 256, 256>>>(W1);     // 1
    k_count<<<(E + 255) / 256, 256>>>(ei, E);                // 2
    k_scan1<<<nb, 1024>>>(M);                                // 3
    k_scan2<<<1, 128>>>(nb);                                 // 4
    k_scan3<<<(M + 255) / 256, 256>>>(M, E);                 // 5

    dim3 g1(HID / 128, (M + 127) / 128);
    k_gemm1<<<g1, 256>>>(features, M);                       // 6  <- profiled
    k_bucket<<<(E + 255) / 256, 256>>>(ei, E);               // 7
    k_agg1<<<M, 256>>>(M);                                   // 8
    k_gemm2<<<(M + 127) / 128, 256>>>(W2, b1, M);            // 9
    k_agg2<<<(M + 7) / 8, 256>>>(M);                         // 10
    k_softmax<<<(M + 7) / 8, 256>>>(b2, out, M, write_soft); // 11
}